// round 2
// baseline (speedup 1.0000x reference)
#include <cuda_runtime.h>
#include <math.h>
#include <stdint.h>

// ============================================================================
// SAE forward: y, loss, fvu
//   x[1024,768] -> encodings = (x*s - b_post + b_pre) @ W_enc[768,32768]
//   top-64 -> sparse decode with W_dec[32768,768]; aux top-128 over dead feats
// ============================================================================

#define BATCH 1024
#define DM 768
#define NF 32768
#define TOPK 64
#define AUXK 128
#define DEAD_AFTER 1000
#define AUX_COEFF 0.03125f

// ---------------- scratch (device globals; no allocation allowed) -----------
__device__ float g_pre[BATCH * DM];
__device__ float g_xn[BATCH * DM];
__device__ float g_enc[(size_t)BATCH * NF];      // 134 MB
__device__ float g_w[BATCH * TOPK];
__device__ int   g_idx[BATCH * TOPK];
__device__ float g_aw[BATCH * AUXK];
__device__ int   g_aidx[BATCH * AUXK];
__device__ float g_recon[BATCH];
__device__ float g_auxl[BATCH];
__device__ float g_rowxn2[BATCH];

// ---------------- kernel 1: normalize + pre-bias -----------------------------
__global__ void prep_kernel(const float* __restrict__ x,
                            const float* __restrict__ b_pre,
                            const float* __restrict__ b_post,
                            const float* __restrict__ avg_norm)
{
    int i = blockIdx.x * 256 + threadIdx.x;          // 786432 total, exact
    float s = sqrtf((float)DM) / avg_norm[0];
    int d = i % DM;
    float v = x[i] * s;
    g_xn[i] = v;
    g_pre[i] = v - b_post[d] + b_pre[d];
}

// ---------------- kernel 2: SGEMM  C[1024,32768] = A[1024,768] * B[768,32768]
// 128x128 block tile, BK=8, 256 threads, 8x8 per-thread (split 4+4 frags
// for conflict-free LDS.128 on both operands).
#define BM 128
#define BN 128
#define BKK 8

__global__ __launch_bounds__(256, 2)
void sgemm_kernel(const float* __restrict__ B /* W_enc */)
{
    __shared__ float As[BKK][BM];
    __shared__ float Bs[BKK][BN];

    const int tid = threadIdx.x;
    const int m0 = blockIdx.y * BM;
    const int n0 = blockIdx.x * BN;

    // loaders
    const int arow = tid >> 1;            // 0..127
    const int acol = (tid & 1) * 4;       // 0 or 4
    const int brow = tid >> 5;            // 0..7
    const int bcol = (tid & 31) * 4;      // 0..124

    // compute mapping (split frags: rows {ty*4, 64+ty*4}, cols {tx*4, 64+tx*4})
    const int ty = tid >> 4;              // 0..15
    const int tx = tid & 15;              // 0..15

    const float* Aptr = g_pre + (size_t)(m0 + arow) * DM + acol;
    const float* Bptr = B + (size_t)brow * NF + n0 + bcol;

    float acc[8][8];
#pragma unroll
    for (int i = 0; i < 8; i++)
#pragma unroll
        for (int j = 0; j < 8; j++) acc[i][j] = 0.0f;

    for (int k0 = 0; k0 < DM; k0 += BKK) {
        float4 av = *(const float4*)(Aptr + k0);
        float4 bv = *(const float4*)(Bptr + (size_t)k0 * NF);
        As[acol + 0][arow] = av.x;
        As[acol + 1][arow] = av.y;
        As[acol + 2][arow] = av.z;
        As[acol + 3][arow] = av.w;
        *(float4*)&Bs[brow][bcol] = bv;
        __syncthreads();

#pragma unroll
        for (int kk = 0; kk < BKK; ++kk) {
            float a[8], b[8];
            *(float4*)(a)     = *(const float4*)&As[kk][ty * 4];
            *(float4*)(a + 4) = *(const float4*)&As[kk][64 + ty * 4];
            *(float4*)(b)     = *(const float4*)&Bs[kk][tx * 4];
            *(float4*)(b + 4) = *(const float4*)&Bs[kk][64 + tx * 4];
#pragma unroll
            for (int i = 0; i < 8; i++)
#pragma unroll
                for (int j = 0; j < 8; j++)
                    acc[i][j] += a[i] * b[j];
        }
        __syncthreads();
    }

    // epilogue
#pragma unroll
    for (int ih = 0; ih < 2; ih++) {
#pragma unroll
        for (int ii = 0; ii < 4; ii++) {
            int m = m0 + ih * 64 + ty * 4 + ii;
            float* Crow = g_enc + (size_t)m * NF + n0;
            int ai = ih * 4 + ii;
            *(float4*)(Crow + tx * 4) =
                make_float4(acc[ai][0], acc[ai][1], acc[ai][2], acc[ai][3]);
            *(float4*)(Crow + 64 + tx * 4) =
                make_float4(acc[ai][4], acc[ai][5], acc[ai][6], acc[ai][7]);
        }
    }
}

// ---------------- kernel 3: per-row exact top-K via byte radix-select --------
__device__ __forceinline__ unsigned fkey(float f)
{
    unsigned u = __float_as_uint(f);
    return u ^ ((u & 0x80000000u) ? 0xFFFFFFFFu : 0x80000000u);
}

#define TOPK_SMEM (NF * 4 + (NF / 32) * 4 + 256 * 4)

__global__ void topk_kernel(const int* __restrict__ act)
{
    extern __shared__ unsigned smem_u[];
    float*    vals = (float*)smem_u;              // NF floats
    unsigned* dmask = smem_u + NF;                // NF/32 words
    unsigned* hist = dmask + (NF / 32);           // 256 bins

    __shared__ unsigned s_prefix, s_krem, s_cnt, s_cnt2, s_total;

    const int row = blockIdx.x;
    const int tid = threadIdx.x;
    const float* encrow = g_enc + (size_t)row * NF;

    if (tid == 0) s_total = 0;

    // load row + build dead bitmask
    for (int i = tid; i < NF; i += 256) {
        vals[i] = encrow[i];
        unsigned b = __ballot_sync(0xffffffffu, act[i] > DEAD_AFTER);
        if ((tid & 31) == 0) dmask[i >> 5] = b;
    }
    __syncthreads();

    // count dead
    {
        unsigned loc = 0;
        for (int w = tid; w < NF / 32; w += 256) loc += __popc(dmask[w]);
        atomicAdd(&s_total, loc);
    }

    // ---------------- main top-64 ----------------
    unsigned prefix = 0, krem = TOPK;
    for (int shift = 24; shift >= 0; shift -= 8) {
        for (int b = tid; b < 256; b += 256) hist[b] = 0;
        __syncthreads();
        unsigned hm = (shift == 24) ? 0u : (0xFFFFFFFFu << (shift + 8));
        for (int i = tid; i < NF; i += 256) {
            unsigned k = fkey(vals[i]);
            if ((k & hm) == prefix) atomicAdd(&hist[(k >> shift) & 255u], 1u);
        }
        __syncthreads();
        if (tid == 0) {
            unsigned cum = 0; int b = 255;
            while (b > 0) {
                unsigned c = hist[b];
                if (cum + c >= krem) break;
                cum += c; --b;
            }
            s_prefix = prefix | ((unsigned)b << shift);
            s_krem = krem - cum;
        }
        __syncthreads();
        prefix = s_prefix; krem = s_krem;
        __syncthreads();
    }
    {
        unsigned T = prefix;
        if (tid == 0) { s_cnt = 0; s_cnt2 = 0; }
        __syncthreads();
        unsigned base_gt = TOPK - krem;
        for (int i = tid; i < NF; i += 256) {
            unsigned k = fkey(vals[i]);
            if (k > T) {
                unsigned p = atomicAdd(&s_cnt, 1u);
                g_w[row * TOPK + p] = vals[i];
                g_idx[row * TOPK + p] = i;
            } else if (k == T) {
                unsigned p = atomicAdd(&s_cnt2, 1u);
                if (p < krem) {
                    g_w[row * TOPK + base_gt + p] = vals[i];
                    g_idx[row * TOPK + base_gt + p] = i;
                }
            }
        }
        __syncthreads();
    }

    // ---------------- aux top-128 among dead ----------------
    unsigned ndead = s_total;
    unsigned asel = ndead < (unsigned)AUXK ? ndead : (unsigned)AUXK;

    if (asel > 0) {
        prefix = 0; krem = asel;
        for (int shift = 24; shift >= 0; shift -= 8) {
            for (int b = tid; b < 256; b += 256) hist[b] = 0;
            __syncthreads();
            unsigned hm = (shift == 24) ? 0u : (0xFFFFFFFFu << (shift + 8));
            for (int i = tid; i < NF; i += 256) {
                if (!((dmask[i >> 5] >> (i & 31)) & 1u)) continue;
                unsigned k = fkey(vals[i]);
                if ((k & hm) == prefix) atomicAdd(&hist[(k >> shift) & 255u], 1u);
            }
            __syncthreads();
            if (tid == 0) {
                unsigned cum = 0; int b = 255;
                while (b > 0) {
                    unsigned c = hist[b];
                    if (cum + c >= krem) break;
                    cum += c; --b;
                }
                s_prefix = prefix | ((unsigned)b << shift);
                s_krem = krem - cum;
            }
            __syncthreads();
            prefix = s_prefix; krem = s_krem;
            __syncthreads();
        }
        unsigned T = prefix;
        if (tid == 0) { s_cnt = 0; s_cnt2 = 0; }
        __syncthreads();
        unsigned base_gt = asel - krem;
        for (int i = tid; i < NF; i += 256) {
            if (!((dmask[i >> 5] >> (i & 31)) & 1u)) continue;
            unsigned k = fkey(vals[i]);
            if (k > T) {
                unsigned p = atomicAdd(&s_cnt, 1u);
                g_aw[row * AUXK + p] = vals[i];
                g_aidx[row * AUXK + p] = i;
            } else if (k == T) {
                unsigned p = atomicAdd(&s_cnt2, 1u);
                if (p < krem) {
                    g_aw[row * AUXK + base_gt + p] = vals[i];
                    g_aidx[row * AUXK + base_gt + p] = i;
                }
            }
        }
        __syncthreads();
    }
    // fill unused aux slots with weight 0 (contribution zero, matches nan_to_num)
    for (int p = (int)asel + tid; p < AUXK; p += 256) {
        g_aw[row * AUXK + p] = 0.0f;
        g_aidx[row * AUXK + p] = 0;
    }
}

// ---------------- kernel 4: sparse decode + per-row losses -------------------
__global__ void decode_kernel(const float* __restrict__ W_dec,
                              const float* __restrict__ b_post,
                              const float* __restrict__ avg_norm,
                              float* __restrict__ out)
{
    const int row = blockIdx.x;
    const int tid = threadIdx.x;   // 256 threads, 3 d-elements each

    __shared__ float sw[TOPK];
    __shared__ int   sidx[TOPK];
    __shared__ float saw[AUXK];
    __shared__ int   said[AUXK];
    __shared__ float red[256];

    if (tid < TOPK)  { sw[tid] = g_w[row * TOPK + tid];  sidx[tid] = g_idx[row * TOPK + tid]; }
    if (tid < AUXK)  { saw[tid] = g_aw[row * AUXK + tid]; said[tid] = g_aidx[row * AUXK + tid]; }
    __syncthreads();

    float acc0 = 0.f, acc1 = 0.f, acc2 = 0.f;
#pragma unroll 4
    for (int k = 0; k < TOPK; k++) {
        const float* r = W_dec + (size_t)sidx[k] * DM;
        float wk = sw[k];
        acc0 += wk * r[tid];
        acc1 += wk * r[tid + 256];
        acc2 += wk * r[tid + 512];
    }
    float a0 = 0.f, a1 = 0.f, a2 = 0.f;
#pragma unroll 4
    for (int k = 0; k < AUXK; k++) {
        const float* r = W_dec + (size_t)said[k] * DM;
        float wk = saw[k];
        a0 += wk * r[tid];
        a1 += wk * r[tid + 256];
        a2 += wk * r[tid + 512];
    }

    float bp0 = b_post[tid], bp1 = b_post[tid + 256], bp2 = b_post[tid + 512];
    float yn0 = acc0 + bp0, yn1 = acc1 + bp1, yn2 = acc2 + bp2;
    float x0 = g_xn[row * DM + tid];
    float x1 = g_xn[row * DM + tid + 256];
    float x2 = g_xn[row * DM + tid + 512];

    float d0 = x0 - yn0, d1 = x1 - yn1, d2 = x2 - yn2;
    float e0 = yn0 - x0 - a0, e1 = yn1 - x1 - a1, e2 = yn2 - x2 - a2;

    // deterministic block reductions
    float rsum, asum, xsum;
    red[tid] = d0 * d0 + d1 * d1 + d2 * d2; __syncthreads();
    for (int s = 128; s > 0; s >>= 1) { if (tid < s) red[tid] += red[tid + s]; __syncthreads(); }
    rsum = red[0]; __syncthreads();
    red[tid] = e0 * e0 + e1 * e1 + e2 * e2; __syncthreads();
    for (int s = 128; s > 0; s >>= 1) { if (tid < s) red[tid] += red[tid + s]; __syncthreads(); }
    asum = red[0]; __syncthreads();
    red[tid] = x0 * x0 + x1 * x1 + x2 * x2; __syncthreads();
    for (int s = 128; s > 0; s >>= 1) { if (tid < s) red[tid] += red[tid + s]; __syncthreads(); }
    xsum = red[0]; __syncthreads();

    float yscale = avg_norm[0] / sqrtf((float)DM);
    out[row * DM + tid]       = yn0 * yscale;
    out[row * DM + tid + 256] = yn1 * yscale;
    out[row * DM + tid + 512] = yn2 * yscale;

    if (tid == 0) {
        g_recon[row] = rsum / (float)DM;
        g_auxl[row] = asum / (float)DM;
        g_rowxn2[row] = xsum;
    }
}

// ---------------- kernel 5: finalize loss + fvu ------------------------------
__global__ void finalize_kernel(const int* __restrict__ act, float* __restrict__ out)
{
    const int tid = threadIdx.x;   // 1024 threads, 1 block
    __shared__ float red[1024];
    __shared__ int s_flag;
    if (tid == 0) s_flag = 0;
    __syncthreads();

    int any = 0;
    for (int i = tid; i < NF; i += 1024) any |= (act[i] > DEAD_AFTER);
    if (any) atomicOr(&s_flag, 1);

    red[tid] = g_recon[tid]; __syncthreads();
    for (int s = 512; s > 0; s >>= 1) { if (tid < s) red[tid] += red[tid + s]; __syncthreads(); }
    float sumr = red[0]; __syncthreads();
    red[tid] = g_rowxn2[tid]; __syncthreads();
    for (int s = 512; s > 0; s >>= 1) { if (tid < s) red[tid] += red[tid + s]; __syncthreads(); }
    float sumx = red[0]; __syncthreads();

    float auxc = s_flag ? AUX_COEFF : 0.0f;
    out[BATCH * DM + tid] = g_recon[tid] + auxc * g_auxl[tid];
    if (tid == 0)
        out[BATCH * DM + BATCH] = sumr * (float)DM / sumx;   // fvu
}

// ---------------- launch -----------------------------------------------------
extern "C" void kernel_launch(void* const* d_in, const int* in_sizes, int n_in,
                              void* d_out, int out_size)
{
    const float* x        = (const float*)d_in[0];
    const float* W_enc    = (const float*)d_in[1];
    const float* W_dec    = (const float*)d_in[2];
    const float* b_pre    = (const float*)d_in[3];
    const float* b_post   = (const float*)d_in[4];
    const float* avg_norm = (const float*)d_in[5];
    const int*   act      = (const int*)d_in[6];
    float* out = (float*)d_out;

    cudaFuncSetAttribute(topk_kernel, cudaFuncAttributeMaxDynamicSharedMemorySize, TOPK_SMEM);

    prep_kernel<<<(BATCH * DM) / 256, 256>>>(x, b_pre, b_post, avg_norm);
    sgemm_kernel<<<dim3(NF / BN, BATCH / BM), 256>>>(W_enc);
    topk_kernel<<<BATCH, 256, TOPK_SMEM>>>(act);
    decode_kernel<<<BATCH, 256>>>(W_dec, b_post, avg_norm, out);
    finalize_kernel<<<1, 1024>>>(act, out);
}

// round 7
// speedup vs baseline: 1.4091x; 1.4091x over previous
#include <cuda_runtime.h>
#include <cuda_bf16.h>
#include <math.h>
#include <stdint.h>

// ============================================================================
// SAE forward: encoder GEMM as bf16x3 split (K tripled to 2304) on mma.sync
// HMMA (plain PTX, no "a"-features), then exact top-64 / aux top-128 + decode.
// ============================================================================

#define BATCH 1024
#define DM 768
#define NF 32768
#define TOPK 64
#define AUXK 128
#define DEAD_AFTER 1000
#define AUX_COEFF 0.03125f

#define KEFF 2304          // 3 * DM  (A: hi|hi|lo,  B: hi|lo|hi)

// ---------------- scratch (device globals; no allocation allowed) -----------
__device__ float g_xn[BATCH * DM];
__device__ __align__(128) __nv_bfloat16 g_As[BATCH * KEFF];          // 4.7 MB
__device__ __align__(128) __nv_bfloat16 g_Bs[(size_t)NF * KEFF];     // 151 MB
__device__ float g_enc[(size_t)BATCH * NF];                          // 134 MB
__device__ float g_w[BATCH * TOPK];
__device__ int   g_idx[BATCH * TOPK];
__device__ float g_aw[BATCH * AUXK];
__device__ int   g_aidx[BATCH * AUXK];
__device__ float g_recon[BATCH];
__device__ float g_auxl[BATCH];
__device__ float g_rowxn2[BATCH];

// ---------------- kernel 1: normalize + pre-bias + A split ------------------
__global__ void prep_kernel(const float* __restrict__ x,
                            const float* __restrict__ b_pre,
                            const float* __restrict__ b_post,
                            const float* __restrict__ avg_norm)
{
    int i = blockIdx.x * 256 + threadIdx.x;          // BATCH*DM total, exact
    float s = sqrtf((float)DM) / avg_norm[0];
    int d = i % DM;
    int m = i / DM;
    float v = x[i] * s;
    g_xn[i] = v;
    float p = v - b_post[d] + b_pre[d];
    __nv_bfloat16 hi = __float2bfloat16(p);
    __nv_bfloat16 lo = __float2bfloat16(p - __bfloat162float(hi));
    g_As[(size_t)m * KEFF + d]          = hi;
    g_As[(size_t)m * KEFF + DM + d]     = hi;
    g_As[(size_t)m * KEFF + 2 * DM + d] = lo;
}

// ---------------- kernel 1b: W_enc transpose + bf16 split -------------------
// W_enc [768, 32768] (n contiguous) -> g_Bs [32768, 2304] (k contiguous)
__global__ void bsplit_kernel(const float* __restrict__ W)
{
    __shared__ float t[32][33];
    int n0 = blockIdx.x * 32;
    int k0 = blockIdx.y * 32;
    int tx = threadIdx.x & 31;
    int ty = threadIdx.x >> 5;   // 0..7
#pragma unroll
    for (int r = 0; r < 4; r++)
        t[ty + r * 8][tx] = W[(size_t)(k0 + ty + r * 8) * NF + n0 + tx];
    __syncthreads();
#pragma unroll
    for (int r = 0; r < 4; r++) {
        int n = n0 + ty + r * 8;
        int k = k0 + tx;
        float v = t[tx][ty + r * 8];
        __nv_bfloat16 hi = __float2bfloat16(v);
        __nv_bfloat16 lo = __float2bfloat16(v - __bfloat162float(hi));
        size_t base = (size_t)n * KEFF;
        g_Bs[base + k]          = hi;   // pairs with A hi
        g_Bs[base + DM + k]     = lo;   // pairs with A hi
        g_Bs[base + 2 * DM + k] = hi;   // pairs with A lo
    }
}

// ---------------- kernel 2: bf16 mma.sync GEMM ------------------------------
// C[1024,32768] = A'[1024,2304] * B'[32768,2304]^T, fp32 accum.
#define BM 128
#define BN 128
#define BK 64
#define NCHUNK (KEFF / BK)     // 36
#define STAGEB (BM * BK * 2 + BN * BK * 2)   // 32768 bytes (A 16K + B 16K)
#define NSTAGE 3
#define GEMM_SMEM (NSTAGE * STAGEB)          // 98304

__device__ __forceinline__ uint32_t s2u(const void* p)
{
    uint32_t a;
    asm("{ .reg .u64 t; cvta.to.shared.u64 t, %1; cvt.u32.u64 %0, t; }" : "=r"(a) : "l"(p));
    return a;
}

__device__ __forceinline__ void cpa16(uint32_t dst, const void* src)
{
    asm volatile("cp.async.cg.shared.global [%0], [%1], 16;" :: "r"(dst), "l"(src) : "memory");
}

__device__ __forceinline__ void ldsm4(uint32_t& r0, uint32_t& r1, uint32_t& r2, uint32_t& r3,
                                      uint32_t addr)
{
    asm volatile("ldmatrix.sync.aligned.m8n8.x4.shared.b16 {%0,%1,%2,%3}, [%4];"
                 : "=r"(r0), "=r"(r1), "=r"(r2), "=r"(r3) : "r"(addr));
}

__device__ __forceinline__ void mma16816(float* c, const uint32_t* a, const uint32_t* b)
{
    asm volatile("mma.sync.aligned.m16n8k16.row.col.f32.bf16.bf16.f32 "
                 "{%0,%1,%2,%3}, {%4,%5,%6,%7}, {%8,%9}, {%0,%1,%2,%3};"
                 : "+f"(c[0]), "+f"(c[1]), "+f"(c[2]), "+f"(c[3])
                 : "r"(a[0]), "r"(a[1]), "r"(a[2]), "r"(a[3]), "r"(b[0]), "r"(b[1]));
}

__global__ void __launch_bounds__(256) gemm_kernel()
{
    extern __shared__ char smem[];
    const uint32_t sbase = s2u(smem);
    const int tid = threadIdx.x;
    const int wid = tid >> 5;
    const int lid = tid & 31;
    const int m0 = blockIdx.x * BM;
    const int n0 = blockIdx.y * BN;
    const int wm = (wid >> 2) * 64;      // warp m-offset (2 warps in m)
    const int wn = (wid & 3) * 32;       // warp n-offset (4 warps in n)

    const __nv_bfloat16* Ab = g_As + (size_t)m0 * KEFF;
    const __nv_bfloat16* Bb = g_Bs + (size_t)n0 * KEFF;

    // ---- loader mapping: 256 threads, 16B each; tile rows 128 x 128B ----
    const int lr = tid >> 3;             // 0..31, rows step +32
    const int lc = tid & 7;              // 16B column within 128B row
    const uint32_t lcol = lc * 16;

    auto load_chunk = [&](int ci, int st) {
        uint32_t s0 = sbase + st * STAGEB;
        const __nv_bfloat16* ap = Ab + ci * BK + lc * 8;
        const __nv_bfloat16* bp = Bb + ci * BK + lc * 8;
#pragma unroll
        for (int j = 0; j < 4; j++) {
            int r = lr + j * 32;
            uint32_t sw = r * 128 + (lcol ^ ((r << 4) & 0x70));
            cpa16(s0 + sw, ap + (size_t)r * KEFF);
        }
#pragma unroll
        for (int j = 0; j < 4; j++) {
            int r = lr + j * 32;
            uint32_t sw = r * 128 + (lcol ^ ((r << 4) & 0x70));
            cpa16(s0 + 16384 + sw, bp + (size_t)r * KEFF);
        }
        asm volatile("cp.async.commit_group;" ::: "memory");
    };

    // ---- ldmatrix lane addressing (swizzle xor is row-only) ----
    const int g = lid >> 3;              // ldmatrix address group 0..3
    const int r8 = lid & 7;
    // A tiles: x4 groups -> (m lo8/k lo8),(m hi8/k lo8),(m lo8/k hi8),(m hi8/k hi8)
    uint32_t aRow[4], aXor[4];
#pragma unroll
    for (int mt = 0; mt < 4; mt++) {
        int row = wm + mt * 16 + (g & 1) * 8 + r8;
        aRow[mt] = row * 128;
        aXor[mt] = (row << 4) & 0x70;
    }
    const uint32_t aColG = (g >> 1) * 16;
    // B tiles: x4 groups -> (n lo8/k lo8),(n lo8/k hi8),(n hi8/k lo8),(n hi8/k hi8)
    uint32_t bRow[2], bXor[2];
#pragma unroll
    for (int ng = 0; ng < 2; ng++) {
        int row = wn + ng * 16 + (g >> 1) * 8 + r8;
        bRow[ng] = row * 128;
        bXor[ng] = (row << 4) & 0x70;
    }
    const uint32_t bColG = (g & 1) * 16;

    float acc[4][4][4];
#pragma unroll
    for (int i = 0; i < 4; i++)
#pragma unroll
        for (int j = 0; j < 4; j++)
#pragma unroll
            for (int q = 0; q < 4; q++) acc[i][j][q] = 0.0f;

    load_chunk(0, 0);
    load_chunk(1, 1);

    for (int i = 0; i < NCHUNK; i++) {
        __syncthreads();                         // stage (i+2)%3 free to overwrite
        if (i + 2 < NCHUNK) load_chunk(i + 2, (i + 2) % NSTAGE);
        asm volatile("cp.async.wait_group 2;" ::: "memory");   // chunk i resident
        __syncthreads();

        uint32_t sb = sbase + (i % NSTAGE) * STAGEB;
        uint32_t sbB = sb + 16384;
#pragma unroll
        for (int ks = 0; ks < 4; ks++) {
            uint32_t kbyte = ks * 32;
            uint32_t aF[4][4];
#pragma unroll
            for (int mt = 0; mt < 4; mt++)
                ldsm4(aF[mt][0], aF[mt][1], aF[mt][2], aF[mt][3],
                      sb + aRow[mt] + ((kbyte + aColG) ^ aXor[mt]));
            uint32_t bF[4][2];
#pragma unroll
            for (int ng = 0; ng < 2; ng++) {
                uint32_t q0, q1, q2, q3;
                ldsm4(q0, q1, q2, q3, sbB + bRow[ng] + ((kbyte + bColG) ^ bXor[ng]));
                bF[2 * ng][0] = q0; bF[2 * ng][1] = q1;
                bF[2 * ng + 1][0] = q2; bF[2 * ng + 1][1] = q3;
            }
#pragma unroll
            for (int mt = 0; mt < 4; mt++)
#pragma unroll
                for (int nt = 0; nt < 4; nt++)
                    mma16816(acc[mt][nt], aF[mt], bF[nt]);
        }
    }

    // ---- epilogue: write C to g_enc ----
    const int erow = lid >> 2;
    const int ecol = (lid & 3) * 2;
#pragma unroll
    for (int mt = 0; mt < 4; mt++) {
        int m = m0 + wm + mt * 16 + erow;
        float* base = g_enc + (size_t)m * NF + n0 + wn + ecol;
#pragma unroll
        for (int nt = 0; nt < 4; nt++) {
            *(float2*)(base + nt * 8) = make_float2(acc[mt][nt][0], acc[mt][nt][1]);
            *(float2*)(base + (size_t)8 * NF + nt * 8) = make_float2(acc[mt][nt][2], acc[mt][nt][3]);
        }
    }
}

// ---------------- kernel 3: per-row exact top-K via byte radix-select --------
__device__ __forceinline__ unsigned fkey(float f)
{
    unsigned u = __float_as_uint(f);
    return u ^ ((u & 0x80000000u) ? 0xFFFFFFFFu : 0x80000000u);
}

#define TOPK_SMEM (NF * 4 + (NF / 32) * 4 + 256 * 4)

__global__ void topk_kernel(const int* __restrict__ act)
{
    extern __shared__ unsigned smem_u[];
    float*    vals = (float*)smem_u;              // NF floats
    unsigned* dmask = smem_u + NF;                // NF/32 words
    unsigned* hist = dmask + (NF / 32);           // 256 bins

    __shared__ unsigned s_prefix, s_krem, s_cnt, s_cnt2, s_total;

    const int row = blockIdx.x;
    const int tid = threadIdx.x;
    const float* encrow = g_enc + (size_t)row * NF;

    if (tid == 0) s_total = 0;

    for (int i = tid; i < NF; i += 256) {
        vals[i] = encrow[i];
        unsigned b = __ballot_sync(0xffffffffu, act[i] > DEAD_AFTER);
        if ((tid & 31) == 0) dmask[i >> 5] = b;
    }
    __syncthreads();

    {
        unsigned loc = 0;
        for (int w = tid; w < NF / 32; w += 256) loc += __popc(dmask[w]);
        atomicAdd(&s_total, loc);
    }

    // ---------------- main top-64 ----------------
    unsigned prefix = 0, krem = TOPK;
    for (int shift = 24; shift >= 0; shift -= 8) {
        for (int b = tid; b < 256; b += 256) hist[b] = 0;
        __syncthreads();
        unsigned hm = (shift == 24) ? 0u : (0xFFFFFFFFu << (shift + 8));
        for (int i = tid; i < NF; i += 256) {
            unsigned k = fkey(vals[i]);
            if ((k & hm) == prefix) atomicAdd(&hist[(k >> shift) & 255u], 1u);
        }
        __syncthreads();
        if (tid == 0) {
            unsigned cum = 0; int b = 255;
            while (b > 0) {
                unsigned c = hist[b];
                if (cum + c >= krem) break;
                cum += c; --b;
            }
            s_prefix = prefix | ((unsigned)b << shift);
            s_krem = krem - cum;
        }
        __syncthreads();
        prefix = s_prefix; krem = s_krem;
        __syncthreads();
    }
    {
        unsigned T = prefix;
        if (tid == 0) { s_cnt = 0; s_cnt2 = 0; }
        __syncthreads();
        unsigned base_gt = TOPK - krem;
        for (int i = tid; i < NF; i += 256) {
            unsigned k = fkey(vals[i]);
            if (k > T) {
                unsigned p = atomicAdd(&s_cnt, 1u);
                g_w[row * TOPK + p] = vals[i];
                g_idx[row * TOPK + p] = i;
            } else if (k == T) {
                unsigned p = atomicAdd(&s_cnt2, 1u);
                if (p < krem) {
                    g_w[row * TOPK + base_gt + p] = vals[i];
                    g_idx[row * TOPK + base_gt + p] = i;
                }
            }
        }
        __syncthreads();
    }

    // ---------------- aux top-128 among dead ----------------
    unsigned ndead = s_total;
    unsigned asel = ndead < (unsigned)AUXK ? ndead : (unsigned)AUXK;

    if (asel > 0) {
        prefix = 0; krem = asel;
        for (int shift = 24; shift >= 0; shift -= 8) {
            for (int b = tid; b < 256; b += 256) hist[b] = 0;
            __syncthreads();
            unsigned hm = (shift == 24) ? 0u : (0xFFFFFFFFu << (shift + 8));
            for (int i = tid; i < NF; i += 256) {
                if (!((dmask[i >> 5] >> (i & 31)) & 1u)) continue;
                unsigned k = fkey(vals[i]);
                if ((k & hm) == prefix) atomicAdd(&hist[(k >> shift) & 255u], 1u);
            }
            __syncthreads();
            if (tid == 0) {
                unsigned cum = 0; int b = 255;
                while (b > 0) {
                    unsigned c = hist[b];
                    if (cum + c >= krem) break;
                    cum += c; --b;
                }
                s_prefix = prefix | ((unsigned)b << shift);
                s_krem = krem - cum;
            }
            __syncthreads();
            prefix = s_prefix; krem = s_krem;
            __syncthreads();
        }
        unsigned T = prefix;
        if (tid == 0) { s_cnt = 0; s_cnt2 = 0; }
        __syncthreads();
        unsigned base_gt = asel - krem;
        for (int i = tid; i < NF; i += 256) {
            if (!((dmask[i >> 5] >> (i & 31)) & 1u)) continue;
            unsigned k = fkey(vals[i]);
            if (k > T) {
                unsigned p = atomicAdd(&s_cnt, 1u);
                g_aw[row * AUXK + p] = vals[i];
                g_aidx[row * AUXK + p] = i;
            } else if (k == T) {
                unsigned p = atomicAdd(&s_cnt2, 1u);
                if (p < krem) {
                    g_aw[row * AUXK + base_gt + p] = vals[i];
                    g_aidx[row * AUXK + base_gt + p] = i;
                }
            }
        }
        __syncthreads();
    }
    for (int p = (int)asel + tid; p < AUXK; p += 256) {
        g_aw[row * AUXK + p] = 0.0f;
        g_aidx[row * AUXK + p] = 0;
    }
}

// ---------------- kernel 4: sparse decode + per-row losses -------------------
__global__ void decode_kernel(const float* __restrict__ W_dec,
                              const float* __restrict__ b_post,
                              const float* __restrict__ avg_norm,
                              float* __restrict__ out)
{
    const int row = blockIdx.x;
    const int tid = threadIdx.x;   // 256 threads, 3 d-elements each

    __shared__ float sw[TOPK];
    __shared__ int   sidx[TOPK];
    __shared__ float saw[AUXK];
    __shared__ int   said[AUXK];
    __shared__ float red[256];

    if (tid < TOPK)  { sw[tid] = g_w[row * TOPK + tid];  sidx[tid] = g_idx[row * TOPK + tid]; }
    if (tid < AUXK)  { saw[tid] = g_aw[row * AUXK + tid]; said[tid] = g_aidx[row * AUXK + tid]; }
    __syncthreads();

    float acc0 = 0.f, acc1 = 0.f, acc2 = 0.f;
#pragma unroll 4
    for (int k = 0; k < TOPK; k++) {
        const float* r = W_dec + (size_t)sidx[k] * DM;
        float wk = sw[k];
        acc0 += wk * r[tid];
        acc1 += wk * r[tid + 256];
        acc2 += wk * r[tid + 512];
    }
    float a0 = 0.f, a1 = 0.f, a2 = 0.f;
#pragma unroll 4
    for (int k = 0; k < AUXK; k++) {
        const float* r = W_dec + (size_t)said[k] * DM;
        float wk = saw[k];
        a0 += wk * r[tid];
        a1 += wk * r[tid + 256];
        a2 += wk * r[tid + 512];
    }

    float bp0 = b_post[tid], bp1 = b_post[tid + 256], bp2 = b_post[tid + 512];
    float yn0 = acc0 + bp0, yn1 = acc1 + bp1, yn2 = acc2 + bp2;
    float x0 = g_xn[row * DM + tid];
    float x1 = g_xn[row * DM + tid + 256];
    float x2 = g_xn[row * DM + tid + 512];

    float d0 = x0 - yn0, d1 = x1 - yn1, d2 = x2 - yn2;
    float e0 = yn0 - x0 - a0, e1 = yn1 - x1 - a1, e2 = yn2 - x2 - a2;

    float rsum, asum, xsum;
    red[tid] = d0 * d0 + d1 * d1 + d2 * d2; __syncthreads();
    for (int s = 128; s > 0; s >>= 1) { if (tid < s) red[tid] += red[tid + s]; __syncthreads(); }
    rsum = red[0]; __syncthreads();
    red[tid] = e0 * e0 + e1 * e1 + e2 * e2; __syncthreads();
    for (int s = 128; s > 0; s >>= 1) { if (tid < s) red[tid] += red[tid + s]; __syncthreads(); }
    asum = red[0]; __syncthreads();
    red[tid] = x0 * x0 + x1 * x1 + x2 * x2; __syncthreads();
    for (int s = 128; s > 0; s >>= 1) { if (tid < s) red[tid] += red[tid + s]; __syncthreads(); }
    xsum = red[0]; __syncthreads();

    float yscale = avg_norm[0] / sqrtf((float)DM);
    out[row * DM + tid]       = yn0 * yscale;
    out[row * DM + tid + 256] = yn1 * yscale;
    out[row * DM + tid + 512] = yn2 * yscale;

    if (tid == 0) {
        g_recon[row] = rsum / (float)DM;
        g_auxl[row] = asum / (float)DM;
        g_rowxn2[row] = xsum;
    }
}

// ---------------- kernel 5: finalize loss + fvu ------------------------------
__global__ void finalize_kernel(const int* __restrict__ act, float* __restrict__ out)
{
    const int tid = threadIdx.x;   // 1024 threads, 1 block
    __shared__ float red[1024];
    __shared__ int s_flag;
    if (tid == 0) s_flag = 0;
    __syncthreads();

    int any = 0;
    for (int i = tid; i < NF; i += 1024) any |= (act[i] > DEAD_AFTER);
    if (any) atomicOr(&s_flag, 1);

    red[tid] = g_recon[tid]; __syncthreads();
    for (int s = 512; s > 0; s >>= 1) { if (tid < s) red[tid] += red[tid + s]; __syncthreads(); }
    float sumr = red[0]; __syncthreads();
    red[tid] = g_rowxn2[tid]; __syncthreads();
    for (int s = 512; s > 0; s >>= 1) { if (tid < s) red[tid] += red[tid + s]; __syncthreads(); }
    float sumx = red[0]; __syncthreads();

    float auxc = s_flag ? AUX_COEFF : 0.0f;
    out[BATCH * DM + tid] = g_recon[tid] + auxc * g_auxl[tid];
    if (tid == 0)
        out[BATCH * DM + BATCH] = sumr * (float)DM / sumx;   // fvu
}

// ---------------- launch -----------------------------------------------------
extern "C" void kernel_launch(void* const* d_in, const int* in_sizes, int n_in,
                              void* d_out, int out_size)
{
    const float* x        = (const float*)d_in[0];
    const float* W_enc    = (const float*)d_in[1];
    const float* W_dec    = (const float*)d_in[2];
    const float* b_pre    = (const float*)d_in[3];
    const float* b_post   = (const float*)d_in[4];
    const float* avg_norm = (const float*)d_in[5];
    const int*   act      = (const int*)d_in[6];
    float* out = (float*)d_out;

    cudaFuncSetAttribute(topk_kernel, cudaFuncAttributeMaxDynamicSharedMemorySize, TOPK_SMEM);
    cudaFuncSetAttribute(gemm_kernel, cudaFuncAttributeMaxDynamicSharedMemorySize, GEMM_SMEM);

    prep_kernel<<<(BATCH * DM) / 256, 256>>>(x, b_pre, b_post, avg_norm);
    bsplit_kernel<<<dim3(NF / 32, DM / 32), 256>>>(W_enc);
    gemm_kernel<<<dim3(BATCH / BM, NF / BN), 256, GEMM_SMEM>>>();
    topk_kernel<<<BATCH, 256, TOPK_SMEM>>>(act);
    decode_kernel<<<BATCH, 256>>>(W_dec, b_post, avg_norm, out);
    finalize_kernel<<<1, 1024>>>(act, out);
}

// round 10
// speedup vs baseline: 2.9895x; 2.1216x over previous
#include <cuda_runtime.h>
#include <cuda_bf16.h>
#include <math.h>
#include <stdint.h>

// ============================================================================
// SAE forward: encoder GEMM as bf16x3 split (K tripled to 2304) on mma.sync
// HMMA; two-scan histogram top-k; sparse decode + losses.
// ============================================================================

#define BATCH 1024
#define DM 768
#define NF 32768
#define TOPK 64
#define AUXK 128
#define DEAD_AFTER 1000
#define AUX_COEFF 0.03125f

#define KEFF 2304          // 3 * DM  (A: hi|hi|lo,  B: hi|lo|hi)

// ---------------- scratch (device globals; no allocation allowed) -----------
__device__ float g_xn[BATCH * DM];
__device__ __align__(128) __nv_bfloat16 g_As[BATCH * KEFF];          // 4.7 MB
__device__ __align__(128) __nv_bfloat16 g_Bs[(size_t)NF * KEFF];     // 151 MB
__device__ float g_enc[(size_t)BATCH * NF];                          // 134 MB
__device__ unsigned g_dmask[NF / 32];
__device__ float g_w[BATCH * TOPK];
__device__ int   g_idx[BATCH * TOPK];
__device__ float g_aw[BATCH * AUXK];
__device__ int   g_aidx[BATCH * AUXK];
__device__ float g_recon[BATCH];
__device__ float g_auxl[BATCH];
__device__ float g_rowxn2[BATCH];

// ---------------- kernel 1: normalize + pre-bias + A split ------------------
__global__ void prep_kernel(const float* __restrict__ x,
                            const float* __restrict__ b_pre,
                            const float* __restrict__ b_post,
                            const float* __restrict__ avg_norm)
{
    int i = blockIdx.x * 256 + threadIdx.x;          // BATCH*DM total, exact
    float s = sqrtf((float)DM) / avg_norm[0];
    int d = i % DM;
    int m = i / DM;
    float v = x[i] * s;
    g_xn[i] = v;
    float p = v - b_post[d] + b_pre[d];
    __nv_bfloat16 hi = __float2bfloat16(p);
    __nv_bfloat16 lo = __float2bfloat16(p - __bfloat162float(hi));
    g_As[(size_t)m * KEFF + d]          = hi;
    g_As[(size_t)m * KEFF + DM + d]     = hi;
    g_As[(size_t)m * KEFF + 2 * DM + d] = lo;
}

// ---------------- kernel 1b: W_enc transpose + bf16 split -------------------
__global__ void bsplit_kernel(const float* __restrict__ W)
{
    __shared__ float t[32][33];
    int n0 = blockIdx.x * 32;
    int k0 = blockIdx.y * 32;
    int tx = threadIdx.x & 31;
    int ty = threadIdx.x >> 5;   // 0..7
#pragma unroll
    for (int r = 0; r < 4; r++)
        t[ty + r * 8][tx] = W[(size_t)(k0 + ty + r * 8) * NF + n0 + tx];
    __syncthreads();
#pragma unroll
    for (int r = 0; r < 4; r++) {
        int n = n0 + ty + r * 8;
        int k = k0 + tx;
        float v = t[tx][ty + r * 8];
        __nv_bfloat16 hi = __float2bfloat16(v);
        __nv_bfloat16 lo = __float2bfloat16(v - __bfloat162float(hi));
        size_t base = (size_t)n * KEFF;
        g_Bs[base + k]          = hi;
        g_Bs[base + DM + k]     = lo;
        g_Bs[base + 2 * DM + k] = hi;
    }
}

// ---------------- kernel 1c: dead bitmask (once) -----------------------------
__global__ void dmask_kernel(const int* __restrict__ act)
{
    int i = blockIdx.x * 256 + threadIdx.x;
    unsigned b = __ballot_sync(0xffffffffu, act[i] > DEAD_AFTER);
    if ((threadIdx.x & 31) == 0) g_dmask[i >> 5] = b;
}

// ---------------- kernel 2: bf16 mma.sync GEMM ------------------------------
#define BM 128
#define BN 128
#define BK 64
#define NCHUNK (KEFF / BK)     // 36
#define STAGEB (BM * BK * 2 + BN * BK * 2)   // 32768 bytes
#define NSTAGE 3
#define GEMM_SMEM (NSTAGE * STAGEB)          // 98304

__device__ __forceinline__ uint32_t s2u(const void* p)
{
    uint32_t a;
    asm("{ .reg .u64 t; cvta.to.shared.u64 t, %1; cvt.u32.u64 %0, t; }" : "=r"(a) : "l"(p));
    return a;
}

__device__ __forceinline__ void cpa16(uint32_t dst, const void* src)
{
    asm volatile("cp.async.cg.shared.global [%0], [%1], 16;" :: "r"(dst), "l"(src) : "memory");
}

__device__ __forceinline__ void ldsm4(uint32_t& r0, uint32_t& r1, uint32_t& r2, uint32_t& r3,
                                      uint32_t addr)
{
    asm volatile("ldmatrix.sync.aligned.m8n8.x4.shared.b16 {%0,%1,%2,%3}, [%4];"
                 : "=r"(r0), "=r"(r1), "=r"(r2), "=r"(r3) : "r"(addr));
}

__device__ __forceinline__ void mma16816(float* c, const uint32_t* a, const uint32_t* b)
{
    asm volatile("mma.sync.aligned.m16n8k16.row.col.f32.bf16.bf16.f32 "
                 "{%0,%1,%2,%3}, {%4,%5,%6,%7}, {%8,%9}, {%0,%1,%2,%3};"
                 : "+f"(c[0]), "+f"(c[1]), "+f"(c[2]), "+f"(c[3])
                 : "r"(a[0]), "r"(a[1]), "r"(a[2]), "r"(a[3]), "r"(b[0]), "r"(b[1]));
}

__global__ void __launch_bounds__(256) gemm_kernel()
{
    extern __shared__ char smem[];
    const uint32_t sbase = s2u(smem);
    const int tid = threadIdx.x;
    const int wid = tid >> 5;
    const int lid = tid & 31;
    const int m0 = blockIdx.x * BM;
    const int n0 = blockIdx.y * BN;
    const int wm = (wid >> 2) * 64;
    const int wn = (wid & 3) * 32;

    const __nv_bfloat16* Ab = g_As + (size_t)m0 * KEFF;
    const __nv_bfloat16* Bb = g_Bs + (size_t)n0 * KEFF;

    const int lr = tid >> 3;
    const int lc = tid & 7;
    const uint32_t lcol = lc * 16;

    auto load_chunk = [&](int ci, int st) {
        uint32_t s0 = sbase + st * STAGEB;
        const __nv_bfloat16* ap = Ab + ci * BK + lc * 8;
        const __nv_bfloat16* bp = Bb + ci * BK + lc * 8;
#pragma unroll
        for (int j = 0; j < 4; j++) {
            int r = lr + j * 32;
            uint32_t sw = r * 128 + (lcol ^ ((r << 4) & 0x70));
            cpa16(s0 + sw, ap + (size_t)r * KEFF);
        }
#pragma unroll
        for (int j = 0; j < 4; j++) {
            int r = lr + j * 32;
            uint32_t sw = r * 128 + (lcol ^ ((r << 4) & 0x70));
            cpa16(s0 + 16384 + sw, bp + (size_t)r * KEFF);
        }
        asm volatile("cp.async.commit_group;" ::: "memory");
    };

    const int g = lid >> 3;
    const int r8 = lid & 7;
    uint32_t aRow[4], aXor[4];
#pragma unroll
    for (int mt = 0; mt < 4; mt++) {
        int row = wm + mt * 16 + (g & 1) * 8 + r8;
        aRow[mt] = row * 128;
        aXor[mt] = (row << 4) & 0x70;
    }
    const uint32_t aColG = (g >> 1) * 16;
    uint32_t bRow[2], bXor[2];
#pragma unroll
    for (int ng = 0; ng < 2; ng++) {
        int row = wn + ng * 16 + (g >> 1) * 8 + r8;
        bRow[ng] = row * 128;
        bXor[ng] = (row << 4) & 0x70;
    }
    const uint32_t bColG = (g & 1) * 16;

    float acc[4][4][4];
#pragma unroll
    for (int i = 0; i < 4; i++)
#pragma unroll
        for (int j = 0; j < 4; j++)
#pragma unroll
            for (int q = 0; q < 4; q++) acc[i][j][q] = 0.0f;

    load_chunk(0, 0);
    load_chunk(1, 1);

    for (int i = 0; i < NCHUNK; i++) {
        __syncthreads();
        if (i + 2 < NCHUNK) load_chunk(i + 2, (i + 2) % NSTAGE);
        asm volatile("cp.async.wait_group 2;" ::: "memory");
        __syncthreads();

        uint32_t sb = sbase + (i % NSTAGE) * STAGEB;
        uint32_t sbB = sb + 16384;
#pragma unroll
        for (int ks = 0; ks < 4; ks++) {
            uint32_t kbyte = ks * 32;
            uint32_t aF[4][4];
#pragma unroll
            for (int mt = 0; mt < 4; mt++)
                ldsm4(aF[mt][0], aF[mt][1], aF[mt][2], aF[mt][3],
                      sb + aRow[mt] + ((kbyte + aColG) ^ aXor[mt]));
            uint32_t bF[4][2];
#pragma unroll
            for (int ng = 0; ng < 2; ng++) {
                uint32_t q0, q1, q2, q3;
                ldsm4(q0, q1, q2, q3, sbB + bRow[ng] + ((kbyte + bColG) ^ bXor[ng]));
                bF[2 * ng][0] = q0; bF[2 * ng][1] = q1;
                bF[2 * ng + 1][0] = q2; bF[2 * ng + 1][1] = q3;
            }
#pragma unroll
            for (int mt = 0; mt < 4; mt++)
#pragma unroll
                for (int nt = 0; nt < 4; nt++)
                    mma16816(acc[mt][nt], aF[mt], bF[nt]);
        }
    }

    const int erow = lid >> 2;
    const int ecol = (lid & 3) * 2;
#pragma unroll
    for (int mt = 0; mt < 4; mt++) {
        int m = m0 + wm + mt * 16 + erow;
        float* base = g_enc + (size_t)m * NF + n0 + wn + ecol;
#pragma unroll
        for (int nt = 0; nt < 4; nt++) {
            *(float2*)(base + nt * 8) = make_float2(acc[mt][nt][0], acc[mt][nt][1]);
            *(float2*)(base + (size_t)8 * NF + nt * 8) = make_float2(acc[mt][nt][2], acc[mt][nt][3]);
        }
    }
}

// ---------------- kernel 3: two-scan histogram top-k -------------------------
__device__ __forceinline__ unsigned fkey(float f)
{
    unsigned u = __float_as_uint(f);
    return u ^ (((unsigned)((int)u >> 31)) | 0x80000000u);
}

#define MCAP 2048

__global__ void __launch_bounds__(1024) topk_kernel()
{
    __shared__ unsigned hist[2048];      // total | dead<<16
    __shared__ unsigned sg[64];          // 32-bin group sums (packed)
    __shared__ float candv[MCAP];
    __shared__ int   candi[MCAP];
    __shared__ float acandv[MCAP];
    __shared__ int   acandi[MCAP];
    __shared__ unsigned s_cm_out, s_cm_cand, s_ca_out, s_ca_cand;
    __shared__ int s_tbm, s_cgtm, s_tba, s_cgta, s_asel;

    const int row = blockIdx.x;
    const int tid = threadIdx.x;
    const float4* enc4 = (const float4*)(g_enc + (size_t)row * NF);

    hist[tid] = 0; hist[tid + 1024] = 0;
    if (tid == 0) { s_cm_out = 0; s_cm_cand = 0; s_ca_out = 0; s_ca_cand = 0; }
    __syncthreads();

    // ---- scan 1: packed histogram ----
    for (int i4 = tid; i4 < NF / 4; i4 += 1024) {
        float4 v = enc4[i4];
        unsigned bits = (g_dmask[i4 >> 3] >> ((i4 & 7) * 4)) & 0xFu;
        atomicAdd(&hist[fkey(v.x) >> 21], 1u | ((bits & 1u) << 16));
        atomicAdd(&hist[fkey(v.y) >> 21], 1u | ((bits & 2u) << 15));
        atomicAdd(&hist[fkey(v.z) >> 21], 1u | ((bits & 4u) << 14));
        atomicAdd(&hist[fkey(v.w) >> 21], 1u | ((bits & 8u) << 13));
    }
    __syncthreads();

    // ---- group sums ----
    if (tid < 64) {
        unsigned s = 0;
#pragma unroll 8
        for (int b = 0; b < 32; b++) s += hist[tid * 32 + b];
        sg[tid] = s;
    }
    __syncthreads();

    // ---- threshold search: main by thread 0, aux by thread 32 ----
    if (tid == 0) {
        unsigned cum = 0; int g = 63;
        for (; g > 0; g--) {
            unsigned c = sg[g] & 0xFFFFu;
            if (cum + c >= (unsigned)TOPK) break;
            cum += c;
        }
        int b = g * 32 + 31;
        for (; b > g * 32; b--) {
            unsigned c = hist[b] & 0xFFFFu;
            if (cum + c >= (unsigned)TOPK) break;
            cum += c;
        }
        s_tbm = b; s_cgtm = (int)cum;
    } else if (tid == 32) {
        unsigned nd = 0;
        for (int g2 = 0; g2 < 64; g2++) nd += sg[g2] >> 16;
        int asel = nd < (unsigned)AUXK ? (int)nd : AUXK;
        s_asel = asel;
        if (asel > 0) {
            unsigned cum = 0; int g = 63;
            for (; g > 0; g--) {
                unsigned c = sg[g] >> 16;
                if (cum + c >= (unsigned)asel) break;
                cum += c;
            }
            int b = g * 32 + 31;
            for (; b > g * 32; b--) {
                unsigned c = hist[b] >> 16;
                if (cum + c >= (unsigned)asel) break;
                cum += c;
            }
            s_tba = b; s_cgta = (int)cum;
        } else { s_tba = 0x7FFFFFFF; s_cgta = 0; }
    }
    __syncthreads();

    const int tbm = s_tbm;
    const int tba = s_tba;
    const int asel = s_asel;
    float* rowW = g_w + row * TOPK;
    int*   rowI = g_idx + row * TOPK;
    float* rowAW = g_aw + row * AUXK;
    int*   rowAI = g_aidx + row * AUXK;

    // ---- scan 2: gather ----
    for (int i4 = tid; i4 < NF / 4; i4 += 1024) {
        float4 v = enc4[i4];
        unsigned bits = (g_dmask[i4 >> 3] >> ((i4 & 7) * 4)) & 0xFu;
        int i = i4 * 4;
#pragma unroll
        for (int j = 0; j < 4; j++) {
            float val = (j == 0) ? v.x : (j == 1) ? v.y : (j == 2) ? v.z : v.w;
            int bin = (int)(fkey(val) >> 21);
            if (bin >= tbm) {
                if (bin > tbm) {
                    unsigned p = atomicAdd(&s_cm_out, 1u);
                    rowW[p] = val; rowI[p] = i + j;
                } else {
                    unsigned p = atomicAdd(&s_cm_cand, 1u);
                    if (p < MCAP) { candv[p] = val; candi[p] = i + j; }
                }
            }
            if ((bits >> j) & 1u) {
                if (bin >= tba) {
                    if (bin > tba) {
                        unsigned p = atomicAdd(&s_ca_out, 1u);
                        rowAW[p] = val; rowAI[p] = i + j;
                    } else {
                        unsigned p = atomicAdd(&s_ca_cand, 1u);
                        if (p < MCAP) { acandv[p] = val; acandi[p] = i + j; }
                    }
                }
            }
        }
    }
    __syncthreads();

    // ---- refinement: warp 0 = main, warp 1 = aux, rest zero-fill aux tail ----
    const int wid = tid >> 5;
    const int lane = tid & 31;
    if (wid == 0) {
        int nc = min((int)s_cm_cand, MCAP);
        int kr = TOPK - s_cgtm;
        int base = s_cgtm;
        for (int s = 0; s < kr; s++) {
            float bv = -3.4e38f; int bp = 0;
            for (int j = lane; j < nc; j += 32) {
                float v = candv[j];
                if (v > bv) { bv = v; bp = j; }
            }
#pragma unroll
            for (int o = 16; o; o >>= 1) {
                float ov = __shfl_xor_sync(0xffffffffu, bv, o);
                int op = __shfl_xor_sync(0xffffffffu, bp, o);
                if (ov > bv) { bv = ov; bp = op; }
            }
            if (lane == 0) {
                rowW[base + s] = bv; rowI[base + s] = candi[bp];
                candv[bp] = -3.4e38f;
            }
            __syncwarp();
        }
    } else if (wid == 1) {
        if (asel > 0) {
            int nc = min((int)s_ca_cand, MCAP);
            int kr = asel - s_cgta;
            int base = s_cgta;
            for (int s = 0; s < kr; s++) {
                float bv = -3.4e38f; int bp = 0;
                for (int j = lane; j < nc; j += 32) {
                    float v = acandv[j];
                    if (v > bv) { bv = v; bp = j; }
                }
#pragma unroll
                for (int o = 16; o; o >>= 1) {
                    float ov = __shfl_xor_sync(0xffffffffu, bv, o);
                    int op = __shfl_xor_sync(0xffffffffu, bp, o);
                    if (ov > bv) { bv = ov; bp = op; }
                }
                if (lane == 0) {
                    rowAW[base + s] = bv; rowAI[base + s] = acandi[bp];
                    acandv[bp] = -3.4e38f;
                }
                __syncwarp();
            }
        }
    } else {
        for (int p = asel + (tid - 64); p < AUXK; p += 1024 - 64) {
            rowAW[p] = 0.0f; rowAI[p] = 0;
        }
    }
}

// ---------------- kernel 4: sparse decode + per-row losses -------------------
__global__ void decode_kernel(const float* __restrict__ W_dec,
                              const float* __restrict__ b_post,
                              const float* __restrict__ avg_norm,
                              float* __restrict__ out)
{
    const int row = blockIdx.x;
    const int tid = threadIdx.x;   // 256 threads, 3 d-elements each

    __shared__ float sw[TOPK];
    __shared__ int   sidx[TOPK];
    __shared__ float saw[AUXK];
    __shared__ int   said[AUXK];
    __shared__ float red[256];

    if (tid < TOPK)  { sw[tid] = g_w[row * TOPK + tid];  sidx[tid] = g_idx[row * TOPK + tid]; }
    if (tid < AUXK)  { saw[tid] = g_aw[row * AUXK + tid]; said[tid] = g_aidx[row * AUXK + tid]; }
    __syncthreads();

    float acc0 = 0.f, acc1 = 0.f, acc2 = 0.f;
#pragma unroll 4
    for (int k = 0; k < TOPK; k++) {
        const float* r = W_dec + (size_t)sidx[k] * DM;
        float wk = sw[k];
        acc0 += wk * r[tid];
        acc1 += wk * r[tid + 256];
        acc2 += wk * r[tid + 512];
    }
    float a0 = 0.f, a1 = 0.f, a2 = 0.f;
#pragma unroll 4
    for (int k = 0; k < AUXK; k++) {
        const float* r = W_dec + (size_t)said[k] * DM;
        float wk = saw[k];
        a0 += wk * r[tid];
        a1 += wk * r[tid + 256];
        a2 += wk * r[tid + 512];
    }

    float bp0 = b_post[tid], bp1 = b_post[tid + 256], bp2 = b_post[tid + 512];
    float yn0 = acc0 + bp0, yn1 = acc1 + bp1, yn2 = acc2 + bp2;
    float x0 = g_xn[row * DM + tid];
    float x1 = g_xn[row * DM + tid + 256];
    float x2 = g_xn[row * DM + tid + 512];

    float d0 = x0 - yn0, d1 = x1 - yn1, d2 = x2 - yn2;
    float e0 = yn0 - x0 - a0, e1 = yn1 - x1 - a1, e2 = yn2 - x2 - a2;

    float rsum, asum, xsum;
    red[tid] = d0 * d0 + d1 * d1 + d2 * d2; __syncthreads();
    for (int s = 128; s > 0; s >>= 1) { if (tid < s) red[tid] += red[tid + s]; __syncthreads(); }
    rsum = red[0]; __syncthreads();
    red[tid] = e0 * e0 + e1 * e1 + e2 * e2; __syncthreads();
    for (int s = 128; s > 0; s >>= 1) { if (tid < s) red[tid] += red[tid + s]; __syncthreads(); }
    asum = red[0]; __syncthreads();
    red[tid] = x0 * x0 + x1 * x1 + x2 * x2; __syncthreads();
    for (int s = 128; s > 0; s >>= 1) { if (tid < s) red[tid] += red[tid + s]; __syncthreads(); }
    xsum = red[0]; __syncthreads();

    float yscale = avg_norm[0] / sqrtf((float)DM);
    out[row * DM + tid]       = yn0 * yscale;
    out[row * DM + tid + 256] = yn1 * yscale;
    out[row * DM + tid + 512] = yn2 * yscale;

    if (tid == 0) {
        g_recon[row] = rsum / (float)DM;
        g_auxl[row] = asum / (float)DM;
        g_rowxn2[row] = xsum;
    }
}

// ---------------- kernel 5: finalize loss + fvu ------------------------------
__global__ void finalize_kernel(const int* __restrict__ act, float* __restrict__ out)
{
    const int tid = threadIdx.x;   // 1024 threads, 1 block
    __shared__ float red[1024];
    __shared__ int s_flag;
    if (tid == 0) s_flag = 0;
    __syncthreads();

    int any = 0;
    for (int i = tid; i < NF; i += 1024) any |= (act[i] > DEAD_AFTER);
    if (any) atomicOr(&s_flag, 1);

    red[tid] = g_recon[tid]; __syncthreads();
    for (int s = 512; s > 0; s >>= 1) { if (tid < s) red[tid] += red[tid + s]; __syncthreads(); }
    float sumr = red[0]; __syncthreads();
    red[tid] = g_rowxn2[tid]; __syncthreads();
    for (int s = 512; s > 0; s >>= 1) { if (tid < s) red[tid] += red[tid + s]; __syncthreads(); }
    float sumx = red[0]; __syncthreads();

    float auxc = s_flag ? AUX_COEFF : 0.0f;
    out[BATCH * DM + tid] = g_recon[tid] + auxc * g_auxl[tid];
    if (tid == 0)
        out[BATCH * DM + BATCH] = sumr * (float)DM / sumx;   // fvu
}

// ---------------- launch -----------------------------------------------------
extern "C" void kernel_launch(void* const* d_in, const int* in_sizes, int n_in,
                              void* d_out, int out_size)
{
    const float* x        = (const float*)d_in[0];
    const float* W_enc    = (const float*)d_in[1];
    const float* W_dec    = (const float*)d_in[2];
    const float* b_pre    = (const float*)d_in[3];
    const float* b_post   = (const float*)d_in[4];
    const float* avg_norm = (const float*)d_in[5];
    const int*   act      = (const int*)d_in[6];
    float* out = (float*)d_out;

    cudaFuncSetAttribute(gemm_kernel, cudaFuncAttributeMaxDynamicSharedMemorySize, GEMM_SMEM);

    prep_kernel<<<(BATCH * DM) / 256, 256>>>(x, b_pre, b_post, avg_norm);
    bsplit_kernel<<<dim3(NF / 32, DM / 32), 256>>>(W_enc);
    dmask_kernel<<<NF / 256, 256>>>(act);
    gemm_kernel<<<dim3(BATCH / BM, NF / BN), 256, GEMM_SMEM>>>();
    topk_kernel<<<BATCH, 1024>>>();
    decode_kernel<<<BATCH, 256>>>(W_dec, b_post, avg_norm, out);
    finalize_kernel<<<1, 1024>>>(act, out);
}